// round 8
// baseline (speedup 1.0000x reference)
#include <cuda_runtime.h>

// SpectralConv2D fused kernel, R8: tap-outer Phase C with 4pos x 4filt register
// accumulators (live set ~35 regs, no spills), transposed y staging.
//   up[b,n]    = mean_c inputs[b,n,c]
//   base[f,p]  = omega[f,i,j] * (lambda_in[i]-lambda_out[j]), p=i*3+j
//   out[b,l,f] = relu( sum_p base[f,p] * (enc[n]-dec[l]) * up[b,n] )
// Block = (batch b, 1 output row = 30 positions, 3 input rows).

#define B_    64
#define W_    32
#define C_    8
#define F_    64
#define O2_   30
#define L_    900
#define N_    1024
#define TILE  30

// per-tap LUTs: p=i*3+j; sel: 0=diag,1=triu,2=tril; t: index within src row
__constant__ int c_sel[9] = {0,1,1,2,0,1,2,2,0};
__constant__ int c_t  [9] = {0,0,1,0,1,2,1,2,2};
__constant__ int c_i  [9] = {0,0,0,1,1,1,2,2,2};
__constant__ int c_j  [9] = {0,1,2,0,1,2,0,1,2};

__global__ __launch_bounds__(128)
void spectral_fused_kernel(
    const float* __restrict__ inputs,      // (B, 32, 32, 8)
    const float* __restrict__ omega_diag,  // (F, 3)
    const float* __restrict__ omega_triu,  // (F*3)
    const float* __restrict__ omega_tril,  // (F*3)
    const float* __restrict__ lambda_in,   // (3)
    const float* __restrict__ lambda_out,  // (3)
    const float* __restrict__ use_encode,  // (N)
    const float* __restrict__ use_decode,  // (L)
    float* __restrict__ out)               // (B, L, F)
{
    __shared__ __align__(16) float up_s[96];        // 3 input rows x 32 cols
    __shared__ __align__(16) float eu_s[96];        // enc*up
    __shared__ __align__(16) float dec_s[32];
    __shared__ __align__(16) float base_s[9 * F_];  // [tap][f]
    __shared__ __align__(16) float y_t[9 * 32];     // TRANSPOSED: [tap][pos]

    const int tid = threadIdx.x;
    const int r0  = blockIdx.x;            // output row 0..29
    const int b   = blockIdx.y;
    const int l0  = r0 * O2_;

    // ---------------- Phase A: input reduce + dec + pad-zero ----------------
    if (tid < 96) {
        int n = (r0 + (tid >> 5)) * W_ + (tid & 31);
        const float4* p = (const float4*)(inputs + ((size_t)b * N_ + n) * C_);
        float4 v0 = p[0];
        float4 v1 = p[1];
        float m = (v0.x + v0.y + v0.z + v0.w + v1.x + v1.y + v1.z + v1.w) * 0.125f;
        up_s[tid] = m;
        eu_s[tid] = m * __ldg(&use_encode[n]);
    } else if (tid < 96 + TILE) {
        dec_s[tid - 96] = __ldg(&use_decode[l0 + tid - 96]);
    }
    // zero the 18 padding entries y_t[tap][30..31] (never stored, keep finite)
    if (tid >= 110 && tid < 128) {
        int k = tid - 110;                 // 0..17
        y_t[(k >> 1) * 32 + 30 + (k & 1)] = 0.f;
    }

    // branchless base assembly: 576 entries over 128 threads, layout [tap][f]
    {
        const float* srcs[3] = { omega_diag, omega_triu, omega_tril };
        #pragma unroll
        for (int k = 0; k < 5; k++) {
            int idx = tid + k * 128;
            if (k < 4 || tid < 64) {
                int pp = idx >> 6;
                int f  = idx & 63;
                float w = __ldg(&srcs[c_sel[pp]][f * 3 + c_t[pp]]);
                float lam = __ldg(&lambda_in[c_i[pp]]) - __ldg(&lambda_out[c_j[pp]]);
                base_s[idx] = w * lam;
            }
        }
    }
    __syncthreads();

    // ---------------- Phase B: y transposed, one thread per position ----------------
    if (tid < TILE) {
        float dec = dec_s[tid];
        int i0 = tid;                      // local col; rows at stride 32
        y_t[0 * 32 + tid] = eu_s[i0 +  0] - dec * up_s[i0 +  0];
        y_t[1 * 32 + tid] = eu_s[i0 +  1] - dec * up_s[i0 +  1];
        y_t[2 * 32 + tid] = eu_s[i0 +  2] - dec * up_s[i0 +  2];
        y_t[3 * 32 + tid] = eu_s[i0 + 32] - dec * up_s[i0 + 32];
        y_t[4 * 32 + tid] = eu_s[i0 + 33] - dec * up_s[i0 + 33];
        y_t[5 * 32 + tid] = eu_s[i0 + 34] - dec * up_s[i0 + 34];
        y_t[6 * 32 + tid] = eu_s[i0 + 64] - dec * up_s[i0 + 64];
        y_t[7 * 32 + tid] = eu_s[i0 + 65] - dec * up_s[i0 + 65];
        y_t[8 * 32 + tid] = eu_s[i0 + 66] - dec * up_s[i0 + 66];
    }
    __syncthreads();

    // ---------------- Phase C: tap-outer, 4 pos x 4 filters per thread ----------------
    const int f4 = tid & 15;               // filter quad
    const int g  = tid >> 4;               // position quad 0..7 (pos = g*4..g*4+3)

    float4 acc0 = make_float4(0.f, 0.f, 0.f, 0.f);
    float4 acc1 = make_float4(0.f, 0.f, 0.f, 0.f);
    float4 acc2 = make_float4(0.f, 0.f, 0.f, 0.f);
    float4 acc3 = make_float4(0.f, 0.f, 0.f, 0.f);

    #pragma unroll
    for (int tap = 0; tap < 9; tap++) {
        float4 wv = *(const float4*)(base_s + tap * F_ + f4 * 4);
        float4 yv = *(const float4*)(y_t + tap * 32 + g * 4);
        acc0.x = fmaf(yv.x, wv.x, acc0.x);
        acc0.y = fmaf(yv.x, wv.y, acc0.y);
        acc0.z = fmaf(yv.x, wv.z, acc0.z);
        acc0.w = fmaf(yv.x, wv.w, acc0.w);
        acc1.x = fmaf(yv.y, wv.x, acc1.x);
        acc1.y = fmaf(yv.y, wv.y, acc1.y);
        acc1.z = fmaf(yv.y, wv.z, acc1.z);
        acc1.w = fmaf(yv.y, wv.w, acc1.w);
        acc2.x = fmaf(yv.z, wv.x, acc2.x);
        acc2.y = fmaf(yv.z, wv.y, acc2.y);
        acc2.z = fmaf(yv.z, wv.z, acc2.z);
        acc2.w = fmaf(yv.z, wv.w, acc2.w);
        acc3.x = fmaf(yv.w, wv.x, acc3.x);
        acc3.y = fmaf(yv.w, wv.y, acc3.y);
        acc3.z = fmaf(yv.w, wv.z, acc3.z);
        acc3.w = fmaf(yv.w, wv.w, acc3.w);
    }

    float* obase = out + ((size_t)b * L_ + l0 + g * 4) * F_ + f4 * 4;
    float4 accs[4] = { acc0, acc1, acc2, acc3 };
    #pragma unroll
    for (int k = 0; k < 4; k++) {
        int pos = g * 4 + k;
        if (pos < TILE) {
            float4 a = accs[k];
            a.x = fmaxf(a.x, 0.f);
            a.y = fmaxf(a.y, 0.f);
            a.z = fmaxf(a.z, 0.f);
            a.w = fmaxf(a.w, 0.f);
            *(float4*)(obase + k * F_) = a;
        }
    }
}

extern "C" void kernel_launch(void* const* d_in, const int* in_sizes, int n_in,
                              void* d_out, int out_size) {
    (void)in_sizes; (void)n_in; (void)out_size;
    const float* inputs      = (const float*)d_in[0];
    const float* omega_diag  = (const float*)d_in[1];
    const float* omega_triu  = (const float*)d_in[2];
    const float* omega_tril  = (const float*)d_in[3];
    const float* lambda_in   = (const float*)d_in[4];
    const float* lambda_out  = (const float*)d_in[5];
    const float* use_encode  = (const float*)d_in[6];
    const float* use_decode  = (const float*)d_in[7];
    float* out = (float*)d_out;

    dim3 grid(O2_, B_);   // (30, 64) = 1920 blocks
    spectral_fused_kernel<<<grid, 128>>>(
        inputs, omega_diag, omega_triu, omega_tril,
        lambda_in, lambda_out, use_encode, use_decode, out);
}

// round 9
// speedup vs baseline: 1.0402x; 1.0402x over previous
#include <cuda_runtime.h>
#include <cstdint>

// SpectralConv2D fused kernel, R9: f32x2 packed FMA (FFMA2), 2 output rows per
// block (halved per-block fixed costs), duplicated-y staging so FFMA2 needs no
// per-tap packing movs.
//   out[b,l,f] = relu( sum_p base[f,p] * (enc[n]-dec[l]) * up[b,n] )

#define B_    64
#define W_    32
#define C_    8
#define F_    64
#define O2_   30
#define L_    900
#define N_    1024
#define TILE  60          // 2 output rows; 4 input rows = 128 px

__constant__ int c_sel[9] = {0,1,1,2,0,1,2,2,0};
__constant__ int c_t  [9] = {0,0,1,0,1,2,1,2,2};
__constant__ int c_i  [9] = {0,0,0,1,1,1,2,2,2};
__constant__ int c_j  [9] = {0,1,2,0,1,2,0,1,2};

__device__ __forceinline__ uint64_t ffma2(uint64_t a, uint64_t b, uint64_t c) {
    uint64_t d;
    asm("fma.rn.f32x2 %0, %1, %2, %3;" : "=l"(d) : "l"(a), "l"(b), "l"(c));
    return d;
}
__device__ __forceinline__ uint64_t fmul2(uint64_t a, uint64_t b) {
    uint64_t d;
    asm("mul.rn.f32x2 %0, %1, %2;" : "=l"(d) : "l"(a), "l"(b));
    return d;
}
__device__ __forceinline__ float2 u64_as_f2(uint64_t v) {
    union { uint64_t u; float2 f; } cv; cv.u = v; return cv.f;
}

__global__ __launch_bounds__(128)
void spectral_fused_kernel(
    const float* __restrict__ inputs,      // (B, 32, 32, 8)
    const float* __restrict__ omega_diag,  // (F, 3)
    const float* __restrict__ omega_triu,  // (F*3)
    const float* __restrict__ omega_tril,  // (F*3)
    const float* __restrict__ lambda_in,   // (3)
    const float* __restrict__ lambda_out,  // (3)
    const float* __restrict__ use_encode,  // (N)
    const float* __restrict__ use_decode,  // (L)
    float* __restrict__ out)               // (B, L, F)
{
    __shared__ __align__(16) float up_s[128];       // 4 input rows x 32
    __shared__ __align__(16) float eu_s[128];       // enc*up
    __shared__ __align__(16) float dec_s[64];
    __shared__ __align__(16) float base_s[9 * F_];  // [tap][f]
    __shared__ __align__(16) float y_d[9 * 128];    // [tap][pos dup x2], pos 0..63

    const int tid = threadIdx.x;
    const int kt  = blockIdx.x;            // 0..14
    const int b   = blockIdx.y;
    const int r0  = kt * 2;
    const int l0  = kt * TILE;

    // ---------------- Phase A: 128 pixels, 1 per thread ----------------
    {
        int n = r0 * W_ + tid;             // rows r0..r0+3
        const float4* p = (const float4*)(inputs + ((size_t)b * N_ + n) * C_);
        float4 v0 = p[0];
        float4 v1 = p[1];
        float m = (v0.x + v0.y + v0.z + v0.w + v1.x + v1.y + v1.z + v1.w) * 0.125f;
        up_s[tid] = m;
        eu_s[tid] = m * __ldg(&use_encode[n]);
    }
    if (tid < TILE)
        dec_s[tid] = __ldg(&use_decode[l0 + tid]);
    // zero-pad duplicated y for positions 60..63 (9 taps x 8 floats = 72)
    if (tid >= 56) {
        int k = tid - 56;                  // 0..71
        y_d[(k >> 3) * 128 + 120 + (k & 7)] = 0.f;
    }

    // branchless base assembly: 576 entries, layout [tap][f]
    {
        const float* srcs[3] = { omega_diag, omega_triu, omega_tril };
        #pragma unroll
        for (int k = 0; k < 5; k++) {
            int idx = tid + k * 128;
            if (k < 4 || tid < 64) {
                int pp = idx >> 6;
                int f  = idx & 63;
                float w = __ldg(&srcs[c_sel[pp]][f * 3 + c_t[pp]]);
                float lam = __ldg(&lambda_in[c_i[pp]]) - __ldg(&lambda_out[c_j[pp]]);
                base_s[idx] = w * lam;
            }
        }
    }
    __syncthreads();

    // ---------------- Phase B: y duplicated, one thread per position ----------------
    if (tid < TILE) {
        float dec = dec_s[tid];
        int i0 = (tid >= 30) ? (tid + 2) : tid;    // orow*32 + ocol
        float2* yd = (float2*)y_d;                  // [tap*64 + pos]
        #pragma unroll
        for (int tap = 0; tap < 9; tap++) {
            const int off = (tap / 3) * 32 + (tap % 3);
            float v = eu_s[i0 + off] - dec * up_s[i0 + off];
            yd[tap * 64 + tid] = make_float2(v, v);
        }
    }
    __syncthreads();

    // ---------------- Phase C: 8 pos x 4 filters, FFMA2 ----------------
    const int f4 = tid & 15;               // filter quad
    const int g  = tid >> 4;               // 0..7 -> positions g*8..g*8+7

    uint64_t acc[8][2];
    #pragma unroll
    for (int tap = 0; tap < 9; tap++) {
        // filters: 2 natural f32x2 pairs
        ulonglong2 wv = *(const ulonglong2*)(base_s + tap * F_ + f4 * 4);
        // 8 duplicated positions: 4 x 16B
        const ulonglong2* yrow = (const ulonglong2*)(y_d + tap * 128 + g * 16);
        ulonglong2 y01 = yrow[0];
        ulonglong2 y23 = yrow[1];
        ulonglong2 y45 = yrow[2];
        ulonglong2 y67 = yrow[3];
        if (tap == 0) {
            acc[0][0] = fmul2(y01.x, wv.x); acc[0][1] = fmul2(y01.x, wv.y);
            acc[1][0] = fmul2(y01.y, wv.x); acc[1][1] = fmul2(y01.y, wv.y);
            acc[2][0] = fmul2(y23.x, wv.x); acc[2][1] = fmul2(y23.x, wv.y);
            acc[3][0] = fmul2(y23.y, wv.x); acc[3][1] = fmul2(y23.y, wv.y);
            acc[4][0] = fmul2(y45.x, wv.x); acc[4][1] = fmul2(y45.x, wv.y);
            acc[5][0] = fmul2(y45.y, wv.x); acc[5][1] = fmul2(y45.y, wv.y);
            acc[6][0] = fmul2(y67.x, wv.x); acc[6][1] = fmul2(y67.x, wv.y);
            acc[7][0] = fmul2(y67.y, wv.x); acc[7][1] = fmul2(y67.y, wv.y);
        } else {
            acc[0][0] = ffma2(y01.x, wv.x, acc[0][0]); acc[0][1] = ffma2(y01.x, wv.y, acc[0][1]);
            acc[1][0] = ffma2(y01.y, wv.x, acc[1][0]); acc[1][1] = ffma2(y01.y, wv.y, acc[1][1]);
            acc[2][0] = ffma2(y23.x, wv.x, acc[2][0]); acc[2][1] = ffma2(y23.x, wv.y, acc[2][1]);
            acc[3][0] = ffma2(y23.y, wv.x, acc[3][0]); acc[3][1] = ffma2(y23.y, wv.y, acc[3][1]);
            acc[4][0] = ffma2(y45.x, wv.x, acc[4][0]); acc[4][1] = ffma2(y45.x, wv.y, acc[4][1]);
            acc[5][0] = ffma2(y45.y, wv.x, acc[5][0]); acc[5][1] = ffma2(y45.y, wv.y, acc[5][1]);
            acc[6][0] = ffma2(y67.x, wv.x, acc[6][0]); acc[6][1] = ffma2(y67.x, wv.y, acc[6][1]);
            acc[7][0] = ffma2(y67.y, wv.x, acc[7][0]); acc[7][1] = ffma2(y67.y, wv.y, acc[7][1]);
        }
    }

    float* obase = out + ((size_t)b * L_ + l0 + g * 8) * F_ + f4 * 4;
    #pragma unroll
    for (int p = 0; p < 8; p++) {
        int pos = g * 8 + p;
        if (pos < TILE) {
            float2 a0 = u64_as_f2(acc[p][0]);
            float2 a1 = u64_as_f2(acc[p][1]);
            float4 o;
            o.x = fmaxf(a0.x, 0.f);
            o.y = fmaxf(a0.y, 0.f);
            o.z = fmaxf(a1.x, 0.f);
            o.w = fmaxf(a1.y, 0.f);
            *(float4*)(obase + p * F_) = o;
        }
    }
}

extern "C" void kernel_launch(void* const* d_in, const int* in_sizes, int n_in,
                              void* d_out, int out_size) {
    (void)in_sizes; (void)n_in; (void)out_size;
    const float* inputs      = (const float*)d_in[0];
    const float* omega_diag  = (const float*)d_in[1];
    const float* omega_triu  = (const float*)d_in[2];
    const float* omega_tril  = (const float*)d_in[3];
    const float* lambda_in   = (const float*)d_in[4];
    const float* lambda_out  = (const float*)d_in[5];
    const float* use_encode  = (const float*)d_in[6];
    const float* use_decode  = (const float*)d_in[7];
    float* out = (float*)d_out;

    dim3 grid(L_ / TILE, B_);   // (15, 64) = 960 blocks
    spectral_fused_kernel<<<grid, 128>>>(
        inputs, omega_diag, omega_triu, omega_tril,
        lambda_in, lambda_out, use_encode, use_decode, out);
}